// round 10
// baseline (speedup 1.0000x reference)
#include <cuda_runtime.h>
#include <cuda_bf16.h>
#include <stdint.h>
#include <math_constants.h>

// Problem shape (fixed)
#define D   512
#define BQ  4096
#define KA  32768
#define H_ELEMS (BQ * D)
#define A_ELEMS (KA * D)

// GEMM tiling: CTA 128x256, K-tile 32, 4-stage cp.async pipeline, 512 threads
#define BM 128
#define BN 256
#define BK 32
#define NSTG 4
#define NKT (D / BK)                      // 16
#define SSTRIDE 40                        // halves per smem row (32 + 8 pad)
#define ROWB (SSTRIDE * 2)                // 80 bytes per row
#define STG_A_ROWS BM
#define STG_B_ROWS BN
#define STG_BYTES ((STG_A_ROWS + STG_B_ROWS) * ROWB)   // 30720
#define SMEM_TOTAL (NSTG * STG_BYTES)                  // 122880
#define WT (KA / 64)                      // 512 warp-n-tiles per row
#define MARGIN 0.15f

// Device scratch
__device__ __nv_bfloat16 g_Hb[H_ELEMS];
__device__ __nv_bfloat16 g_Ab[A_ELEMS];   // A scaled by 1/||a||
__device__ float g_inv_a[KA];
__device__ uint4 g_cand[(size_t)BQ * WT]; // {s1,i1,s2,i2} per (row, 64-col tile)

// ---------------------------------------------------------------------------
__global__ void k_prep_h(const float* __restrict__ H) {
    int i = blockIdx.x * blockDim.x + threadIdx.x;
    float2 v = ((const float2*)H)[i];
    __nv_bfloat162 p = __floats2bfloat162_rn(v.x, v.y);
    ((unsigned*)g_Hb)[i] = *(unsigned*)&p;
}

__global__ void k_prep_a(const float* __restrict__ A) {
    int gw = (blockIdx.x * blockDim.x + threadIdx.x) >> 5;
    int lane = threadIdx.x & 31;
    if (gw >= KA) return;
    const float4* row = (const float4*)(A + (size_t)gw * D);
    float4 v[4]; float s = 0.f;
#pragma unroll
    for (int i = 0; i < 4; i++) {
        v[i] = row[lane + 32 * i];
        s += v[i].x * v[i].x + v[i].y * v[i].y + v[i].z * v[i].z + v[i].w * v[i].w;
    }
#pragma unroll
    for (int o = 16; o; o >>= 1) s += __shfl_xor_sync(0xffffffffu, s, o);
    float inv = 1.0f / fmaxf(sqrtf(s), 1e-8f);
    if (lane == 0) g_inv_a[gw] = inv;
    unsigned* dst = (unsigned*)(g_Ab + (size_t)gw * D);
#pragma unroll
    for (int i = 0; i < 4; i++) {
        __nv_bfloat162 p0 = __floats2bfloat162_rn(v[i].x * inv, v[i].y * inv);
        __nv_bfloat162 p1 = __floats2bfloat162_rn(v[i].z * inv, v[i].w * inv);
        int e = lane + 32 * i;
        dst[2 * e]     = *(unsigned*)&p0;
        dst[2 * e + 1] = *(unsigned*)&p1;
    }
}

// ---------------------------------------------------------------------------
#define MMA16816(d, a0, a1, a2, a3, b0, b1) asm volatile( \
    "mma.sync.aligned.m16n8k16.row.col.f32.bf16.bf16.f32 " \
    "{%0,%1,%2,%3}, {%4,%5,%6,%7}, {%8,%9}, {%0,%1,%2,%3};" \
    : "+f"(d[0]), "+f"(d[1]), "+f"(d[2]), "+f"(d[3]) \
    : "r"(a0), "r"(a1), "r"(a2), "r"(a3), "r"(b0), "r"(b1))

__global__ __launch_bounds__(512, 1) void k_gemm_bf16() {
    extern __shared__ char smem[];
    unsigned sb = (unsigned)__cvta_generic_to_shared(smem);

    int t = threadIdx.x, lane = t & 31, warp = t >> 5;
    int wm = warp >> 2, wn = warp & 3;         // 4 x 4 warp grid; tile 32(m) x 64(n)
    int m0 = blockIdx.y * BM, n0 = blockIdx.x * BN;

    // Loader: 1536 16B-chunks per stage, 3 per thread. row<128 -> A, else B.
    int c0 = t * 3;
    // ldmatrix byte offsets within a stage (pad-40 rows, conflict-free)
    unsigned offA = (unsigned)(wm * 32 + (lane & 15)) * ROWB + ((lane >> 4) * 16);
    unsigned offB = (unsigned)(STG_A_ROWS + wn * 64 + (lane & 7) + ((lane >> 4) * 8)) * ROWB
                    + (((lane >> 3) & 1) * 16);

    float acc[2][8][4];
#pragma unroll
    for (int mi = 0; mi < 2; mi++)
#pragma unroll
        for (int ni = 0; ni < 8; ni++)
#pragma unroll
            for (int c = 0; c < 4; c++) acc[mi][ni][c] = 0.f;

    auto issue = [&](int kt) {
        unsigned stg = sb + (unsigned)(kt & (NSTG - 1)) * STG_BYTES;
#pragma unroll
        for (int i = 0; i < 3; i++) {
            int c = c0 + i;
            int row = c >> 2, seg = c & 3;
            const char* src;
            unsigned dst;
            if (row < STG_A_ROWS) {
                src = (const char*)(g_Hb + (size_t)(m0 + row) * D + kt * BK) + seg * 16;
                dst = stg + (unsigned)row * ROWB + seg * 16;
            } else {
                int br = row - STG_A_ROWS;
                src = (const char*)(g_Ab + (size_t)(n0 + br) * D + kt * BK) + seg * 16;
                dst = stg + (unsigned)row * ROWB + seg * 16;
            }
            asm volatile("cp.async.cg.shared.global [%0], [%1], 16;" :: "r"(dst), "l"(src) : "memory");
        }
        asm volatile("cp.async.commit_group;" ::: "memory");
    };

    // Prologue: stages 0..NSTG-2
#pragma unroll
    for (int s = 0; s < NSTG - 1; s++) issue(s);

    for (int kt = 0; kt < NKT; kt++) {
        asm volatile("cp.async.wait_group %0;" :: "n"(NSTG - 2) : "memory");
        __syncthreads();

        unsigned stg = sb + (unsigned)(kt & (NSTG - 1)) * STG_BYTES;
#pragma unroll
        for (int kf = 0; kf < 2; kf++) {
            unsigned a[2][4], b[4][4];
#pragma unroll
            for (int mi = 0; mi < 2; mi++) {
                unsigned ad = stg + offA + (unsigned)(mi * 16 * ROWB) + kf * 32;
                asm volatile("ldmatrix.sync.aligned.m8n8.x4.shared.b16 {%0,%1,%2,%3}, [%4];"
                             : "=r"(a[mi][0]), "=r"(a[mi][1]), "=r"(a[mi][2]), "=r"(a[mi][3])
                             : "r"(ad));
            }
#pragma unroll
            for (int nj = 0; nj < 4; nj++) {   // each x4 covers 2 n8-tiles
                unsigned bd = stg + offB + (unsigned)(nj * 16 * ROWB) + kf * 32;
                asm volatile("ldmatrix.sync.aligned.m8n8.x4.shared.b16 {%0,%1,%2,%3}, [%4];"
                             : "=r"(b[nj][0]), "=r"(b[nj][1]), "=r"(b[nj][2]), "=r"(b[nj][3])
                             : "r"(bd));
            }
#pragma unroll
            for (int mi = 0; mi < 2; mi++)
#pragma unroll
                for (int nj = 0; nj < 4; nj++) {
                    MMA16816(acc[mi][2 * nj],     a[mi][0], a[mi][1], a[mi][2], a[mi][3],
                             b[nj][0], b[nj][1]);
                    MMA16816(acc[mi][2 * nj + 1], a[mi][0], a[mi][1], a[mi][2], a[mi][3],
                             b[nj][2], b[nj][3]);
                }
        }
        // Next load writes the buffer freed by compute(kt-1); this iteration's
        // syncthreads (above) already ordered all threads past that compute.
        if (kt + NSTG - 1 < NKT) issue(kt + NSTG - 1);
        else asm volatile("cp.async.commit_group;" ::: "memory");  // keep group count
    }

    // Epilogue: per (row, 64-col warp tile) top-2, 4-lane shuffle merge, store.
#pragma unroll
    for (int mi = 0; mi < 2; mi++)
#pragma unroll
        for (int h = 0; h < 2; h++) {
            float s1 = -CUDART_INF_F, s2 = -CUDART_INF_F;
            unsigned i1 = 0, i2 = 0;
#pragma unroll
            for (int ni = 0; ni < 8; ni++)
#pragma unroll
                for (int c = 0; c < 2; c++) {
                    float v = acc[mi][ni][h * 2 + c];
                    unsigned n = (unsigned)(n0 + wn * 64 + ni * 8 + (lane & 3) * 2 + c);
                    if (v > s1) { s2 = s1; i2 = i1; s1 = v; i1 = n; }
                    else if (v > s2) { s2 = v; i2 = n; }
                }
#pragma unroll
            for (int off = 1; off <= 2; off <<= 1) {
                float t1 = __shfl_xor_sync(0xffffffffu, s1, off);
                unsigned j1 = __shfl_xor_sync(0xffffffffu, i1, off);
                float t2 = __shfl_xor_sync(0xffffffffu, s2, off);
                unsigned j2 = __shfl_xor_sync(0xffffffffu, i2, off);
                if (t1 > s1) {
                    float os = s1; unsigned oi = i1;
                    s1 = t1; i1 = j1;
                    if (t2 > os) { s2 = t2; i2 = j2; } else { s2 = os; i2 = oi; }
                } else if (t1 > s2) { s2 = t1; i2 = j1; }
            }
            if ((lane & 3) == 0) {
                int rg = m0 + wm * 32 + mi * 16 + (lane >> 2) + h * 8;
                g_cand[(size_t)rg * WT + (size_t)(blockIdx.x * 4 + wn)] =
                    make_uint4(__float_as_uint(s1), i1, __float_as_uint(s2), i2);
            }
        }
}

// ---------------------------------------------------------------------------
// Per row: approx max over 1024 candidates, fp32-rescore within MARGIN,
// exact argmax (first-index tie-break). One warp per row.
// ---------------------------------------------------------------------------
__global__ void k_select(const float* __restrict__ H, const float* __restrict__ A,
                         float* __restrict__ out) {
    int r = (blockIdx.x * blockDim.x + threadIdx.x) >> 5;
    int lane = threadIdx.x & 31;
    if (r >= BQ) return;
    const uint2* cand = (const uint2*)(g_cand + (size_t)r * WT);   // 1024 entries

    float mx = -CUDART_INF_F;
    for (int j = lane; j < WT * 2; j += 32)
        mx = fmaxf(mx, __uint_as_float(cand[j].x));
#pragma unroll
    for (int o = 16; o; o >>= 1) mx = fmaxf(mx, __shfl_xor_sync(0xffffffffu, mx, o));
    float thr = mx - MARGIN;

    const float4* h4 = (const float4*)(H + (size_t)r * D);
    float4 hv[4];
#pragma unroll
    for (int i = 0; i < 4; i++) hv[i] = h4[lane + 32 * i];

    unsigned long long best = 0ull;
    for (int j0 = 0; j0 < WT * 2; j0 += 32) {
        uint2 c = cand[j0 + lane];
        unsigned m = __ballot_sync(0xffffffffu, __uint_as_float(c.x) >= thr);
        while (m) {
            int src = __ffs(m) - 1; m &= m - 1;
            unsigned idx = __shfl_sync(0xffffffffu, c.y, src);
            const float4* a4 = (const float4*)(A + (size_t)idx * D);
            float p = 0.f;
#pragma unroll
            for (int i = 0; i < 4; i++) {
                float4 av = a4[lane + 32 * i];
                p += hv[i].x * av.x + hv[i].y * av.y + hv[i].z * av.z + hv[i].w * av.w;
            }
#pragma unroll
            for (int o = 16; o; o >>= 1) p += __shfl_xor_sync(0xffffffffu, p, o);
            float s = p * g_inv_a[idx];
            unsigned u = __float_as_uint(s);
            u = (u & 0x80000000u) ? ~u : (u | 0x80000000u);
            unsigned long long key =
                ((unsigned long long)u << 32) | (unsigned long long)(0xFFFFFFFFu - idx);
            if (key > best) best = key;
        }
    }
    if (lane == 0)
        out[r] = (float)(0xFFFFFFFFu - (unsigned)(best & 0xFFFFFFFFull));
}

// ---------------------------------------------------------------------------
extern "C" void kernel_launch(void* const* d_in, const int* in_sizes, int n_in,
                              void* d_out, int out_size) {
    const float* H = (const float*)d_in[0];
    const float* A = (const float*)d_in[1];
    if (n_in >= 2 && in_sizes[0] == A_ELEMS) {   // bind by size
        H = (const float*)d_in[1];
        A = (const float*)d_in[0];
    }

    k_prep_h<<<H_ELEMS / 2 / 256, 256>>>(H);
    k_prep_a<<<KA / 8, 256>>>(A);

    cudaFuncSetAttribute(k_gemm_bf16, cudaFuncAttributeMaxDynamicSharedMemorySize, SMEM_TOTAL);
    dim3 grid(KA / BN, BQ / BM);                 // 128 x 32 = 4096 CTAs
    k_gemm_bf16<<<grid, 512, SMEM_TOTAL>>>();

    k_select<<<BQ / 8, 256>>>(H, A, (float*)d_out);
}